// round 3
// baseline (speedup 1.0000x reference)
#include <cuda_runtime.h>

#define NB 2
#define NS 2048
#define NE 1024
#define NH 16
#define ND 64
#define SC 32       // s-chunks for pv partials
#define SCLEN 64    // s per chunk (SC*SCLEN == NS)

// Scratch (allocation-free: device globals)
__device__ float g_qwk[NB*NH*NE];        // [b][h][e]
__device__ float g_p[NB*NH*NS];          // raw scores
__device__ float g_pvp[NB*SC*NH*NE];     // unnormalized pv partials [b][sc][h][e]
__device__ float g_sump[NB*SC*NH];       // per-chunk exp sums
__device__ float g_o[NB*NE];
__device__ float g_y[NB*NE];

__device__ __forceinline__ float dot4(float4 a, float4 b){
  return fmaf(a.x,b.x, fmaf(a.y,b.y, fmaf(a.z,b.z, a.w*b.w)));
}
__device__ __forceinline__ float warp_sum(float v){
#pragma unroll
  for (int o=16;o>0;o>>=1) v += __shfl_xor_sync(0xffffffffu, v, o);
  return v;
}

// K1: fused q + qwk.  Block (h, b), 512 threads.
__global__ void __launch_bounds__(512) k_qk(const float* __restrict__ inputs,
                                            const float* __restrict__ Wq,
                                            const float* __restrict__ Wk){
  int h = blockIdx.x, b = blockIdx.y;
  __shared__ float qs[ND];
  __shared__ float4 buf[2][256];
  int tid = threadIdx.x, lane = tid & 31, w = tid >> 5;
  const float4* xr = (const float4*)(inputs + ((size_t)b*NS + (NS-1))*NE);
  float acc[4] = {0.f,0.f,0.f,0.f};
  int dbase = w*4;
#pragma unroll
  for (int it=0; it<8; ++it){
    int e4 = lane + it*32;
    float4 x = xr[e4];
#pragma unroll
    for (int k=0;k<4;k++){
      const float4* wr = (const float4*)(Wq + (size_t)(h*ND + dbase + k)*NE);
      acc[k] += dot4(x, wr[e4]);
    }
  }
#pragma unroll
  for (int k=0;k<4;k++){
    float s = warp_sum(acc[k]);
    if (!lane) qs[dbase+k] = s;
  }
  __syncthreads();
  int e4 = tid & 255;
  int dh = tid >> 8;                 // 0 or 1
  const float4* Wk4 = (const float4*)Wk;
  float4 a = make_float4(0.f,0.f,0.f,0.f);
#pragma unroll 8
  for (int dd=0; dd<32; ++dd){
    int d = dh*32 + dd;
    float qv = qs[d];
    float4 wv = Wk4[(size_t)(h*ND + d)*256 + e4];
    a.x = fmaf(qv,wv.x,a.x); a.y = fmaf(qv,wv.y,a.y);
    a.z = fmaf(qv,wv.z,a.z); a.w = fmaf(qv,wv.w,a.w);
  }
  buf[dh][e4] = a;
  __syncthreads();
  if (tid < 256){
    float4 p0 = buf[0][tid], p1 = buf[1][tid];
    float4 r = make_float4(p0.x+p1.x, p0.y+p1.y, p0.z+p1.z, p0.w+p1.w);
    ((float4*)g_qwk)[(size_t)(b*NH + h)*256 + tid] = r;
  }
}

// K2: raw scores[b][h][s] = dot(embK[b,s,:], qwk[b,h,:]); qwk cached in 64KB smem.
__global__ void __launch_bounds__(256) k_scores(const float* __restrict__ embK){
  extern __shared__ float qwk_s[];     // [NH][NE] = 64 KB
  int b = blockIdx.y;
  {
    const float4* src = (const float4*)(g_qwk + (size_t)b*NH*NE);
    float4* dst = (float4*)qwk_s;
#pragma unroll
    for (int i=0;i<16;i++) dst[threadIdx.x + i*256] = src[threadIdx.x + i*256];
  }
  __syncthreads();
  int wid = threadIdx.x >> 5, lane = threadIdx.x & 31;
  int s = blockIdx.x*32 + wid*4;
  const float4* r = (const float4*)(embK + ((size_t)b*NS + s)*NE);
  float acc[NH][4];
#pragma unroll
  for (int h=0;h<NH;h++){
#pragma unroll
    for (int k=0;k<4;k++) acc[h][k]=0.f;
  }
#pragma unroll
  for (int it=0; it<8; ++it){
    int e4 = lane + it*32;
    float4 x0 = r[e4];
    float4 x1 = r[e4 + 256];
    float4 x2 = r[e4 + 512];
    float4 x3 = r[e4 + 768];
#pragma unroll
    for (int h=0; h<NH; ++h){
      float4 w = ((const float4*)qwk_s)[h*256 + e4];
      acc[h][0] += dot4(x0,w);
      acc[h][1] += dot4(x1,w);
      acc[h][2] += dot4(x2,w);
      acc[h][3] += dot4(x3,w);
    }
  }
#pragma unroll
  for (int h=0;h<NH;h++){
#pragma unroll
    for (int k=0;k<4;k++) acc[h][k] = warp_sum(acc[h][k]);
  }
  if (!lane){
#pragma unroll
    for (int h=0;h<NH;h++){
#pragma unroll
      for (int k=0;k<4;k++) g_p[((size_t)b*NH+h)*NS + s + k] = acc[h][k];
    }
  }
}

// K3: unnormalized pv partials with on-the-fly exp.
//   g_pvp[b][sc][h][e] = sum_{s in chunk} exp(score) * embV[b,s,e]
//   g_sump[b][sc][h]   = sum_{s in chunk} exp(score)
// Grid (4 e-chunks, SC, NB), 256 thr = 4 head-groups x 64 e4-threads.
__global__ void __launch_bounds__(256) k_pv(const float* __restrict__ embV){
  int ec = blockIdx.x, sc = blockIdx.y, b = blockIdx.z;
  __shared__ float ps[NH][SCLEN];      // 4 KB
  int tid = threadIdx.x;
  int s0 = sc*SCLEN;
  // load raw scores (16 heads x 64 s = 256 float4), exponentiate
  {
    int h = tid >> 4;                  // 16 float4 per head row
    int s4 = tid & 15;
    float4 r = ((const float4*)(g_p + ((size_t)b*NH+h)*NS + s0))[s4];
    float4 e;
    e.x=__expf(r.x); e.y=__expf(r.y); e.z=__expf(r.z); e.w=__expf(r.w);
    ((float4*)ps[h])[s4] = e;
  }
  __syncthreads();
  if (ec == 0 && tid < NH){
    float su = 0.f;
#pragma unroll
    for (int ss=0; ss<SCLEN; ++ss) su += ps[tid][ss];
    g_sump[((size_t)b*SC + sc)*NH + tid] = su;
  }
  int hg = tid >> 6;                   // head group 0..3 (4 heads each)
  int t64 = tid & 63;
  int e4 = ec*64 + t64;
  int h0 = hg*4;
  const float4* v = (const float4*)(embV + ((size_t)b*NS + s0)*NE) + e4;
  float4 acc[4];
#pragma unroll
  for (int j=0;j<4;j++) acc[j] = make_float4(0.f,0.f,0.f,0.f);
#pragma unroll 4
  for (int ss=0; ss<SCLEN; ++ss){
    float4 x = v[(size_t)ss*256];
#pragma unroll
    for (int j=0;j<4;j++){
      float pw = ps[h0+j][ss];
      acc[j].x = fmaf(pw,x.x,acc[j].x);
      acc[j].y = fmaf(pw,x.y,acc[j].y);
      acc[j].z = fmaf(pw,x.z,acc[j].z);
      acc[j].w = fmaf(pw,x.w,acc[j].w);
    }
  }
  float4* outp = (float4*)g_pvp + ((size_t)(b*SC + sc)*NH)*256 + e4;
#pragma unroll
  for (int j=0;j<4;j++) outp[(h0+j)*256] = acc[j];
}

// K4: fused pv-reduce + o projection.
// Block (ig, h, b), 256 thr: reduce 32 chunks of pv row into smem,
// then 32 outputs i = h*64 + ig*32 + w*4 + k, normalized by row exp-sum.
__global__ void __launch_bounds__(256) k_o(const float* __restrict__ Wv){
  int ig = blockIdx.x, h = blockIdx.y, b = blockIdx.z;
  __shared__ float4 pvs[256];
  __shared__ float invs;
  int tid = threadIdx.x, lane = tid & 31, w = tid >> 5;
  // reduce partials: chunk stride = NH*256 float4
  const float4* src = (const float4*)g_pvp + ((size_t)(b*SC)*NH + h)*256 + tid;
  float4 acc = make_float4(0.f,0.f,0.f,0.f);
#pragma unroll
  for (int c=0;c<SC;c++){
    float4 x = src[(size_t)c*NH*256];
    acc.x+=x.x; acc.y+=x.y; acc.z+=x.z; acc.w+=x.w;
  }
  pvs[tid] = acc;
  if (tid < 32){
    float s = warp_sum(g_sump[((size_t)b*SC + tid)*NH + h]);
    if (!tid) invs = 1.f/s;
  }
  __syncthreads();
  float a[4] = {0.f,0.f,0.f,0.f};
  int ibase = h*64 + ig*32 + w*4;
#pragma unroll
  for (int it=0; it<8; ++it){
    int e4 = lane + it*32;
    float4 x = pvs[e4];
#pragma unroll
    for (int k=0;k<4;k++){
      const float4* wr = (const float4*)(Wv + (size_t)(ibase+k)*NE);
      a[k] += dot4(x, wr[e4]);
    }
  }
  float inv = invs;
#pragma unroll
  for (int k=0;k<4;k++){
    float s = warp_sum(a[k]);
    if (!lane) g_o[b*NE + ibase + k] = s * inv;
  }
}

// K5: g_y[b][j] = dot(g_o[b][:], Wo[j][:])
__global__ void k_y(const float* __restrict__ Wo){
  int gw = (blockIdx.x*blockDim.x + threadIdx.x) >> 5;
  int lane = threadIdx.x & 31;
  int b = gw >> 10, j = gw & 1023;
  const float4* xr = (const float4*)(g_o + (size_t)b*NE);
  const float4* wr = (const float4*)(Wo + (size_t)j*NE);
  float acc = 0.f;
#pragma unroll
  for (int it=0; it<8; ++it) acc += dot4(xr[lane+it*32], wr[lane+it*32]);
  acc = warp_sum(acc);
  if (!lane) g_y[b*NE+j] = acc;
}

// K6: broadcast y row to all S positions
__global__ void k_bcast(float* __restrict__ out){
  int gi = blockIdx.x*blockDim.x + threadIdx.x;  // float4 idx over NB*NS*NE/4
  int e4 = gi & 255;
  int b  = gi >> 19;                              // / (NS*NE/4)
  float4 y = ((const float4*)g_y)[b*256 + e4];
  ((float4*)out)[gi] = y;
}

extern "C" void kernel_launch(void* const* d_in, const int* in_sizes, int n_in,
                              void* d_out, int out_size){
  const float* inputs = (const float*)d_in[0];
  const float* embV   = (const float*)d_in[1];
  const float* embK   = (const float*)d_in[2];
  const float* Wq     = (const float*)d_in[3];
  const float* Wk     = (const float*)d_in[4];
  const float* Wv     = (const float*)d_in[5];
  const float* Wo     = (const float*)d_in[6];
  float* out = (float*)d_out;

  cudaFuncSetAttribute(k_scores, cudaFuncAttributeMaxDynamicSharedMemorySize, 65536);

  k_qk     <<<dim3(NH, NB), 512>>>(inputs, Wq, Wk);
  k_scores <<<dim3(NS/32, NB), 256, 65536>>>(embK);
  k_pv     <<<dim3(4, SC, NB), 256>>>(embV);
  k_o      <<<dim3(2, NH, NB), 256>>>(Wv);
  k_y      <<<256, 256>>>(Wo);
  k_bcast  <<<(NB*NS*NE/4)/256, 256>>>(out);
}

// round 4
// speedup vs baseline: 1.2170x; 1.2170x over previous
#include <cuda_runtime.h>

#define NB 2
#define NS 2048
#define NE 1024
#define NH 16
#define ND 64
#define SC 32       // s-chunks for pv partials
#define SCLEN 64    // s per chunk (SC*SCLEN == NS)

// Scratch (allocation-free: device globals)
__device__ float g_q[NB*NE];
__device__ float g_qwk[NB*NH*NE];        // [b][h][e]
__device__ float g_p[NB*NH*NS];          // raw scores
__device__ float g_pvp[NB*SC*NH*NE];     // unnormalized pv partials [b][sc][h][e]
__device__ float g_sump[NB*SC*NH];       // per-chunk exp sums
__device__ float g_pv[NB*NH*NE];
__device__ float g_o[NB*NE];
__device__ float g_y[NB*NE];

__device__ __forceinline__ float dot4(float4 a, float4 b){
  return fmaf(a.x,b.x, fmaf(a.y,b.y, fmaf(a.z,b.z, a.w*b.w)));
}
__device__ __forceinline__ float warp_sum(float v){
#pragma unroll
  for (int o=16;o>0;o>>=1) v += __shfl_xor_sync(0xffffffffu, v, o);
  return v;
}

// K1: g_q[b][j] = dot(inputs[b, S-1, :], Wq[j, :])  (warp per output, 256 blocks)
__global__ void k_q(const float* __restrict__ inputs, const float* __restrict__ Wq){
  int gw = (blockIdx.x*blockDim.x + threadIdx.x) >> 5;
  int lane = threadIdx.x & 31;
  int b = gw >> 10, j = gw & 1023;
  const float4* xr = (const float4*)(inputs + ((size_t)b*NS + (NS-1))*NE);
  const float4* wr = (const float4*)(Wq + (size_t)j*NE);
  float acc = 0.f;
#pragma unroll
  for (int it=0; it<8; ++it) acc += dot4(xr[lane+it*32], wr[lane+it*32]);
  acc = warp_sum(acc);
  if (!lane) g_q[b*NE+j] = acc;
}

// K2: g_qwk[b][h][e] = sum_d g_q[b][h*64+d] * Wk[h*64+d][e]
// Grid (64, NB): block = (h, e-quarter), 64 threads, no redundant Wk reads.
__global__ void __launch_bounds__(64) k_qwk(const float* __restrict__ Wk){
  int h = blockIdx.x >> 2, eq = blockIdx.x & 3, b = blockIdx.y;
  __shared__ float qs[ND];
  int t = threadIdx.x;
  qs[t] = g_q[b*NE + h*ND + t];
  __syncthreads();
  int e4 = eq*64 + t;
  const float4* Wk4 = (const float4*)Wk;
  float4 a = make_float4(0.f,0.f,0.f,0.f);
#pragma unroll 8
  for (int d=0; d<ND; ++d){
    float qv = qs[d];
    float4 w = Wk4[(size_t)(h*ND + d)*256 + e4];
    a.x = fmaf(qv,w.x,a.x); a.y = fmaf(qv,w.y,a.y);
    a.z = fmaf(qv,w.z,a.z); a.w = fmaf(qv,w.w,a.w);
  }
  ((float4*)g_qwk)[(size_t)(b*NH + h)*256 + e4] = a;
}

// K3: raw scores[b][h][s] = dot(embK[b,s,:], qwk[b,h,:]); qwk cached in 64KB smem.
__global__ void __launch_bounds__(256) k_scores(const float* __restrict__ embK){
  extern __shared__ float qwk_s[];     // [NH][NE] = 64 KB
  int b = blockIdx.y;
  {
    const float4* src = (const float4*)(g_qwk + (size_t)b*NH*NE);
    float4* dst = (float4*)qwk_s;
#pragma unroll
    for (int i=0;i<16;i++) dst[threadIdx.x + i*256] = src[threadIdx.x + i*256];
  }
  __syncthreads();
  int wid = threadIdx.x >> 5, lane = threadIdx.x & 31;
  int s = blockIdx.x*32 + wid*4;
  const float4* r = (const float4*)(embK + ((size_t)b*NS + s)*NE);
  float acc[NH][4];
#pragma unroll
  for (int h=0;h<NH;h++){
#pragma unroll
    for (int k=0;k<4;k++) acc[h][k]=0.f;
  }
#pragma unroll
  for (int it=0; it<8; ++it){
    int e4 = lane + it*32;
    float4 x0 = r[e4];
    float4 x1 = r[e4 + 256];
    float4 x2 = r[e4 + 512];
    float4 x3 = r[e4 + 768];
#pragma unroll
    for (int h=0; h<NH; ++h){
      float4 w = ((const float4*)qwk_s)[h*256 + e4];
      acc[h][0] += dot4(x0,w);
      acc[h][1] += dot4(x1,w);
      acc[h][2] += dot4(x2,w);
      acc[h][3] += dot4(x3,w);
    }
  }
#pragma unroll
  for (int h=0;h<NH;h++){
#pragma unroll
    for (int k=0;k<4;k++) acc[h][k] = warp_sum(acc[h][k]);
  }
  if (!lane){
#pragma unroll
    for (int h=0;h<NH;h++){
#pragma unroll
      for (int k=0;k<4;k++) g_p[((size_t)b*NH+h)*NS + s + k] = acc[h][k];
    }
  }
}

// K4: unnormalized pv partials with on-the-fly exp.
// Grid (4 e-chunks, SC, NB) = 256 blocks, 256 thr = 4 head-groups x 64 e4-threads.
__global__ void __launch_bounds__(256) k_pv(const float* __restrict__ embV){
  int ec = blockIdx.x, sc = blockIdx.y, b = blockIdx.z;
  __shared__ float ps[NH][SCLEN];      // 4 KB
  int tid = threadIdx.x;
  int s0 = sc*SCLEN;
  {
    int h = tid >> 4;                  // 16 float4 per head row
    int s4 = tid & 15;
    float4 r = ((const float4*)(g_p + ((size_t)b*NH+h)*NS + s0))[s4];
    float4 e;
    e.x=__expf(r.x); e.y=__expf(r.y); e.z=__expf(r.z); e.w=__expf(r.w);
    ((float4*)ps[h])[s4] = e;
  }
  __syncthreads();
  if (ec == 0 && tid < NH){
    float su = 0.f;
#pragma unroll
    for (int ss=0; ss<SCLEN; ++ss) su += ps[tid][ss];
    g_sump[((size_t)b*SC + sc)*NH + tid] = su;
  }
  int hg = tid >> 6;                   // head group 0..3 (4 heads each)
  int t64 = tid & 63;
  int e4 = ec*64 + t64;
  int h0 = hg*4;
  const float4* v = (const float4*)(embV + ((size_t)b*NS + s0)*NE) + e4;
  float4 acc[4];
#pragma unroll
  for (int j=0;j<4;j++) acc[j] = make_float4(0.f,0.f,0.f,0.f);
#pragma unroll 4
  for (int ss=0; ss<SCLEN; ++ss){
    float4 x = v[(size_t)ss*256];
#pragma unroll
    for (int j=0;j<4;j++){
      float pw = ps[h0+j][ss];
      acc[j].x = fmaf(pw,x.x,acc[j].x);
      acc[j].y = fmaf(pw,x.y,acc[j].y);
      acc[j].z = fmaf(pw,x.z,acc[j].z);
      acc[j].w = fmaf(pw,x.w,acc[j].w);
    }
  }
  float4* outp = (float4*)g_pvp + ((size_t)(b*SC + sc)*NH)*256 + e4;
#pragma unroll
  for (int j=0;j<4;j++) outp[(h0+j)*256] = acc[j];
}

// K5: reduce pv partials over SC chunks. 256 blocks x 32 threads, 1 output each.
__global__ void __launch_bounds__(32) k_pvred(){
  int i4 = blockIdx.x*32 + threadIdx.x;    // over NB*NH*NE/4 = 8192
  int b = i4 >> 12;
  int r = i4 & 4095;
  const float4* src = (const float4*)g_pvp + (size_t)b*SC*4096 + r;
  float4 acc = make_float4(0.f,0.f,0.f,0.f);
#pragma unroll
  for (int c=0;c<SC;c++){
    float4 x = src[(size_t)c*4096];
    acc.x+=x.x; acc.y+=x.y; acc.z+=x.z; acc.w+=x.w;
  }
  ((float4*)g_pv)[i4] = acc;
}

// K6: g_o[b][i] = dot(g_pv[b][h_i][:], Wv[i][:]) / rowsum[b][h_i]  (256 blocks)
__global__ void k_o(const float* __restrict__ Wv){
  int gw = (blockIdx.x*blockDim.x + threadIdx.x) >> 5;
  int lane = threadIdx.x & 31;
  int b = gw >> 10, i = gw & 1023;
  int h = i >> 6;
  float ssum = warp_sum(g_sump[((size_t)b*SC + lane)*NH + h]);
  const float4* xr = (const float4*)(g_pv + ((size_t)b*NH + h)*NE);
  const float4* wr = (const float4*)(Wv + (size_t)i*NE);
  float acc = 0.f;
#pragma unroll
  for (int it=0; it<8; ++it) acc += dot4(xr[lane+it*32], wr[lane+it*32]);
  acc = warp_sum(acc);
  if (!lane) g_o[b*NE+i] = acc / ssum;
}

// K7: g_y[b][j] = dot(g_o[b][:], Wo[j][:])  (256 blocks)
__global__ void k_y(const float* __restrict__ Wo){
  int gw = (blockIdx.x*blockDim.x + threadIdx.x) >> 5;
  int lane = threadIdx.x & 31;
  int b = gw >> 10, j = gw & 1023;
  const float4* xr = (const float4*)(g_o + (size_t)b*NE);
  const float4* wr = (const float4*)(Wo + (size_t)j*NE);
  float acc = 0.f;
#pragma unroll
  for (int it=0; it<8; ++it) acc += dot4(xr[lane+it*32], wr[lane+it*32]);
  acc = warp_sum(acc);
  if (!lane) g_y[b*NE+j] = acc;
}

// K8: broadcast y row to all S positions (4096 blocks, store-bound)
__global__ void k_bcast(float* __restrict__ out){
  int gi = blockIdx.x*blockDim.x + threadIdx.x;  // float4 idx over NB*NS*NE/4
  int e4 = gi & 255;
  int b  = gi >> 19;                              // / (NS*NE/4)
  float4 y = ((const float4*)g_y)[b*256 + e4];
  ((float4*)out)[gi] = y;
}

extern "C" void kernel_launch(void* const* d_in, const int* in_sizes, int n_in,
                              void* d_out, int out_size){
  const float* inputs = (const float*)d_in[0];
  const float* embV   = (const float*)d_in[1];
  const float* embK   = (const float*)d_in[2];
  const float* Wq     = (const float*)d_in[3];
  const float* Wk     = (const float*)d_in[4];
  const float* Wv     = (const float*)d_in[5];
  const float* Wo     = (const float*)d_in[6];
  float* out = (float*)d_out;

  cudaFuncSetAttribute(k_scores, cudaFuncAttributeMaxDynamicSharedMemorySize, 65536);

  k_q      <<<256, 256>>>(inputs, Wq);
  k_qwk    <<<dim3(64, NB), 64>>>(Wk);
  k_scores <<<dim3(NS/32, NB), 256, 65536>>>(embK);
  k_pv     <<<dim3(4, SC, NB), 256>>>(embV);
  k_pvred  <<<256, 32>>>();
  k_o      <<<256, 256>>>(Wv);
  k_y      <<<256, 256>>>(Wo);
  k_bcast  <<<(NB*NS*NE/4)/256, 256>>>(out);
}